// round 6
// baseline (speedup 1.0000x reference)
#include <cuda_runtime.h>

#define NT    64
#define BATCH 8192

// Per sample: E_w = <Phi| (⊗_{j<=w} O_j) |Phi>,  Phi = CNOT-chain |⊗ phi_j>
// (bond-2 MPS).  O_j = cos^2(t) Z + sin(t)cos(t) Y - sin(t) X, t = params[1][j].
// phi_j = RY(t1) RX(t1) RY(x_j)|0>, t1 = params[0][j].
// Boundary L[c][c'] is HERMITIAN: track L00, L11 (real) and P = L01 (complex).
// Update (derived from N = Phi L Phi^dag, L' = Op(.)N):
//   A=|f0|^2, B=|f1|^2, g=f0*conj(f1)
//   N00 = A L00 + B L11 + 2(gr Pr - gi Pi)
//   N11 = B L00 + A L11 + 2(gr Pr + gi Pi)
//   N01 = ( gr(L00+L11) + (A+B) Pr ,  gi(L00-L11) + (A-B) Pi )
//   L00' = cc N00,  L11' = -cc N11,  P' = (a + i b) * N01
// with a=-sin t, b=sin t cos t, cc=cos^2 t.
// Emission (suffix closure): E_{j-1} = (L00+L11) + X_j * 2 Pr,  X_j = 2 gr_j;
// final E_11 = L00 + L11 + 2 Pr.
__global__ void __launch_bounds__(NT)
qexp_kernel(const float* __restrict__ x, const float* __restrict__ params,
            const float* __restrict__ hw, const float* __restrict__ hb,
            float* __restrict__ out)
{
    const int b = blockIdx.x * NT + threadIdx.x;

    // ---- issue ALL loads up front (one memory epoch, MLP ~13) ----
    const float4* xv = (const float4*)(x + b * 12);       // 48B row, 16B aligned
    const float4 xq0 = xv[0], xq1 = xv[1], xq2 = xv[2];
    const float4* pv = (const float4*)params;             // 24 floats (broadcast)
    const float4 p0 = pv[0], p1 = pv[1], p2 = pv[2];
    const float4 p3 = pv[3], p4 = pv[4], p5 = pv[5];
    const float4* wv = (const float4*)hw;                 // 12 floats (broadcast)
    const float4 w0 = wv[0], w1 = wv[1], w2 = wv[2];
    const float bias = hb[0];

    const float xa[12]  = { xq0.x,xq0.y,xq0.z,xq0.w, xq1.x,xq1.y,xq1.z,xq1.w,
                            xq2.x,xq2.y,xq2.z,xq2.w };
    const float th1[12] = { p0.x,p0.y,p0.z,p0.w, p1.x,p1.y,p1.z,p1.w,
                            p2.x,p2.y,p2.z,p2.w };
    const float th2[12] = { p3.x,p3.y,p3.z,p3.w, p4.x,p4.y,p4.z,p4.w,
                            p5.x,p5.y,p5.z,p5.w };
    const float hwa[12] = { w0.x,w0.y,w0.z,w0.w, w1.x,w1.y,w1.z,w1.w,
                            w2.x,w2.y,w2.z,w2.w };

    // ---- per-wire independent precompute (MUFU-pipelined, high ILP) ----
    // per wire keep: A, B, gr, gi, Oa, Ob, Oc
    float Aq[12], Bq[12], Gr[12], Gi[12], Oa[12], Ob[12], Oc[12];
    #pragma unroll
    for (int j = 0; j < 12; j++){
        float s1, c1; __sincosf(0.5f * th1[j], &s1, &c1);
        float s2, c2; __sincosf(th2[j], &s2, &c2);        // full angle for O
        Oa[j] = -s2; Ob[j] = s2 * c2; Oc[j] = c2 * c2;
        float sx, cx; __sincosf(0.5f * xa[j], &sx, &cx);
        // phi_j = RY(t1) RX(t1) (cx, sx)
        const float f0r =  c1 * (c1 * cx - s1 * sx);
        const float f0i =  s1 * (s1 * cx - c1 * sx);
        const float f1r =  c1 * (s1 * cx + c1 * sx);
        const float f1i = -s1 * (s1 * sx + c1 * cx);
        Aq[j] = f0r * f0r + f0i * f0i;
        Bq[j] = f1r * f1r + f1i * f1i;
        Gr[j] = f0r * f1r + f0i * f1i;      // Re(f0 conj(f1))
        Gi[j] = f0i * f1r - f0r * f1i;      // Im(f0 conj(f1))
    }

    // ---- serial Hermitian transfer sweep (registers only) ----
    float L00 = 1.f, L11 = 0.f, Pr = 0.f, Pi = 0.f;
    float acc = bias;

    #pragma unroll
    for (int j = 0; j < 12; j++){
        const float A = Aq[j], B = Bq[j], gr = Gr[j], gi = Gi[j];

        if (j > 0){
            // E_{j-1} = (L00+L11) + X_j * (2 Pr),  X_j = 2 gr
            const float E = (L00 + L11) + 4.f * gr * Pr;
            acc = fmaf(hwa[j-1], E, acc);
        }

        const float u  = gr * Pr, v = gi * Pi;
        const float N00 = fmaf(A, L00, fmaf(B, L11, 2.f * (u - v)));
        const float N11 = fmaf(B, L00, fmaf(A, L11, 2.f * (u + v)));
        const float N01r = fmaf(gr, L00 + L11, (A + B) * Pr);
        const float N01i = fmaf(gi, L00 - L11, (A - B) * Pi);

        const float a = Oa[j], bb = Ob[j], cc = Oc[j];
        L00 =  cc * N00;
        L11 = -cc * N11;
        Pr  = fmaf(a, N01r, -bb * N01i);
        Pi  = fmaf(a, N01i,  bb * N01r);
    }

    // E_11: empty suffix (X_12 = 1)
    const float E11 = L00 + L11 + 2.f * Pr;
    acc = fmaf(hwa[11], E11, acc);

    out[b] = acc;
}

extern "C" void kernel_launch(void* const* d_in, const int* in_sizes, int n_in,
                              void* d_out, int out_size)
{
    const float* x      = (const float*)d_in[0];   // [8192,12]
    const float* params = (const float*)d_in[1];   // [2,12]
    const float* hw     = (const float*)d_in[2];   // [1,12]
    const float* hb     = (const float*)d_in[3];   // [1]
    float* out          = (float*)d_out;           // [8192,1]
    (void)in_sizes; (void)n_in; (void)out_size;

    qexp_kernel<<<BATCH / NT, NT>>>(x, params, hw, hb, out);
}